// round 15
// baseline (speedup 1.0000x reference)
#include <cuda_runtime.h>
#include <cuda_fp16.h>
#include <cstdint>

// ===================== sizes =====================
#define LL 16384
#define HH 1024
#define H2 2048
#define CCH 32           // scan chunk length (register-resident)
#define GG  (LL/CCH)     // 512 chunks
#define EPS 1e-5f

__device__ __forceinline__ float sigm(float z) { return 1.f / (1.f + expf(-z)); }

// ===================== device scratch (everything fp16 except y) ================
__device__ __half g_hid [(size_t)LL*HH];
__device__ __half g_u   [(size_t)LL*HH];
__device__ __half g_gate[(size_t)LL*HH];
__device__ __half g_st  [(size_t)LL*HH];
__device__ float  g_y[(size_t)LL*HH];
__device__ __half g_h2  [(size_t)LL*HH];
__device__ __half g_ff1 [(size_t)LL*H2];
__device__ __half g_Wug [(size_t)H2*HH];
__device__ __half g_Wout[(size_t)HH*HH];
__device__ __half g_Wff1[(size_t)H2*HH];
__device__ __half g_Wff2[(size_t)HH*H2];
__device__ float g_cf[GG*HH], g_cb[GG*HH], g_sinf[GG*HH], g_sinb[GG*HH];

// ===================== small kernels =====================

// transpose+convert: src [K,N] fp32 -> dst [N,K] fp16. Block tile: 64(K) x 32(N), 256 thr.
__global__ void transpose_h_kernel(const float* __restrict__ src,
                                   __half* __restrict__ dh, int K, int N) {
    __shared__ float tile[64][33];
    int kb = blockIdx.y * 64, nb = blockIdx.x * 32;
    int tid = threadIdx.x;
    int tn = tid & 31, tk = tid >> 5;       // 8 k-rows, step 8
    #pragma unroll
    for (int i = 0; i < 8; i++)
        tile[tk + i*8][tn] = src[(size_t)(kb + tk + i*8) * N + nb + tn];
    __syncthreads();
    int on = tid >> 3, oj = tid & 7;        // 32 n-rows, 8 k-pair slots
    #pragma unroll
    for (int i = 0; i < 4; i++) {
        int kp = (oj + i*8) * 2;
        __half2 v;
        v.x = __float2half(tile[kp][on]);
        v.y = __float2half(tile[kp+1][on]);
        *reinterpret_cast<__half2*>(dh + (size_t)(nb + on) * K + kb + kp) = v;
    }
}

// LayerNorm -> fp16. block = 256 threads, one row per block.
__global__ void ln_h_kernel(const float* __restrict__ x, const float* __restrict__ w,
                            const float* __restrict__ b, __half* __restrict__ oh) {
    __shared__ float red[8];
    int row = blockIdx.x, tid = threadIdx.x;
    const float* xr = x + (size_t)row * HH;
    float v[4];
    float s = 0.f;
    #pragma unroll
    for (int i = 0; i < 4; i++) { v[i] = xr[tid + i*256]; s += v[i]; }
    #pragma unroll
    for (int o = 16; o; o >>= 1) s += __shfl_xor_sync(0xffffffffu, s, o);
    if ((tid & 31) == 0) red[tid >> 5] = s;
    __syncthreads();
    float tot = 0.f;
    #pragma unroll
    for (int i = 0; i < 8; i++) tot += red[i];
    float mean = tot * (1.f / HH);
    __syncthreads();
    float vs = 0.f;
    #pragma unroll
    for (int i = 0; i < 4; i++) { float d = v[i] - mean; vs += d * d; }
    #pragma unroll
    for (int o = 16; o; o >>= 1) vs += __shfl_xor_sync(0xffffffffu, vs, o);
    if ((tid & 31) == 0) red[tid >> 5] = vs;
    __syncthreads();
    float var = 0.f;
    #pragma unroll
    for (int i = 0; i < 8; i++) var += red[i];
    var *= (1.f / HH);
    float rstd = rsqrtf(var + EPS);
    #pragma unroll
    for (int i = 0; i < 4; i++) {
        int idx = tid + i*256;
        float val = (v[i] - mean) * rstd * w[idx] + b[idx];
        oh[(size_t)row * HH + idx] = __float2half(val);
    }
}

// scan pass1: per-chunk carries, u (fp16) register-resident. grid (GG, HH/128), block 128.
__global__ void scan_p1_kernel(const __half* __restrict__ u, const float* __restrict__ sd,
                               float* __restrict__ cf, float* __restrict__ cb) {
    int g = blockIdx.x;
    int c = blockIdx.y * 128 + threadIdx.x;
    float d = sigm(sd[c]);
    const __half* up = u + (size_t)g * CCH * HH + c;
    float vv[CCH];
    #pragma unroll
    for (int t = 0; t < CCH; t++) vv[t] = __half2float(up[(size_t)t * HH]);
    float sf = 0.f, sb = 0.f;
    #pragma unroll
    for (int t = 0; t < CCH; t++) sf = d * sf + vv[t];
    #pragma unroll
    for (int t = CCH - 1; t >= 0; t--) sb = d * sb + vv[t];
    cf[g*HH + c] = sf;
    cb[g*HH + c] = sb;
}

// scan pass2: cross-chunk exclusive scan; blockIdx.y = direction. grid (HH/256, 2), block 256.
__global__ void scan_p2_kernel(const float* __restrict__ cf, const float* __restrict__ cb,
                               const float* __restrict__ sd,
                               float* __restrict__ sinf, float* __restrict__ sinb) {
    int c = blockIdx.x * 256 + threadIdx.x;
    float d = sigm(sd[c]);
    float dC = d;
    #pragma unroll
    for (int i = 0; i < 5; i++) dC *= dC;   // d^32
    if (blockIdx.y == 0) {
        float s = 0.f;
        for (int g = 0; g < GG; g++) { sinf[g*HH + c] = s; s = dC * s + cf[g*HH + c]; }
    } else {
        float s = 0.f;
        for (int g = GG - 1; g >= 0; g--) { sinb[g*HH + c] = s; s = dC * s + cb[g*HH + c]; }
    }
}

// scan pass3 (fused fwd+bwd, register-resident): combine + gate -> fp16.
__global__ void scan_p3_kernel(const __half* __restrict__ u, const __half* __restrict__ gate,
                               const float* __restrict__ sd,
                               const float* __restrict__ sinf, const float* __restrict__ sinb,
                               __half* __restrict__ oh) {
    int g = blockIdx.x;
    int c = blockIdx.y * 128 + threadIdx.x;
    float d = sigm(sd[c]);
    size_t base = (size_t)g * CCH * HH + c;
    float vv[CCH], fs[CCH];
    #pragma unroll
    for (int t = 0; t < CCH; t++) vv[t] = __half2float(u[base + (size_t)t * HH]);
    float s = sinf[g*HH + c];
    #pragma unroll
    for (int t = 0; t < CCH; t++) { s = d * s + vv[t]; fs[t] = s; }
    float sb = sinb[g*HH + c];
    #pragma unroll
    for (int t = CCH - 1; t >= 0; t--) {
        size_t o = base + (size_t)t * HH;
        sb = d * sb + vv[t];
        float so = 0.5f * (fs[t] + sb) * __half2float(gate[o]);
        oh[o] = __float2half(so);
    }
}

// ===================== GEMM (plain fp16, mma.sync + cp.async) =====================
// C[M,N] = A[M,K] * B^T  (B stored [N,K]), fp32 accumulate.
// BM=128, BN=128, BK=64, 256 threads (8 warps 2x4, warp tile 64x32), 3-stage cp.async.
// Cross-chunk fragment pipeline: wait_group(0) + barrier makes slots kc AND kc+1
// visible; entry fragments of chunk kc+1 preloaded during chunk kc.
#define BKK 64
#define GSTAGES 3
#define GTHREADS 256
#define TILE_B 16384                // 128 rows x 64 cols x 2B
#define STAGE_B (2*TILE_B)          // A, B = 32768
#define GSMEM_BYTES (GSTAGES*STAGE_B)   // 98304

// SW128: 128B rows, 8 x 16B chunks, chunk ^= row&7
__device__ __forceinline__ uint32_t sw_off(int row, int chunk) {
    return (uint32_t)(row * 128 + (((chunk ^ row) & 7) << 4));
}
__device__ __forceinline__ uint32_t smem_u32(const void* p) {
    uint32_t a;
    asm("{ .reg .u64 t; cvta.to.shared.u64 t, %1; cvt.u32.u64 %0, t; }" : "=r"(a) : "l"(p));
    return a;
}
__device__ __forceinline__ void cp16(uint32_t saddr, const void* gaddr) {
    asm volatile("cp.async.cg.shared.global [%0], [%1], 16;" :: "r"(saddr), "l"(gaddr));
}
#define CP_COMMIT() asm volatile("cp.async.commit_group;" ::: "memory")
#define CP_WAIT(n)  asm volatile("cp.async.wait_group %0;" :: "n"(n) : "memory")

__device__ __forceinline__ void ldsm4(uint32_t& r0, uint32_t& r1, uint32_t& r2, uint32_t& r3,
                                      uint32_t addr) {
    asm volatile("ldmatrix.sync.aligned.m8n8.x4.shared.b16 {%0,%1,%2,%3}, [%4];"
                 : "=r"(r0), "=r"(r1), "=r"(r2), "=r"(r3) : "r"(addr));
}
__device__ __forceinline__ void mma16816(float* c, const uint32_t* a, const uint32_t* b) {
    asm volatile("mma.sync.aligned.m16n8k16.row.col.f32.f16.f16.f32 "
                 "{%0,%1,%2,%3}, {%4,%5,%6,%7}, {%8,%9}, {%0,%1,%2,%3};"
                 : "+f"(c[0]), "+f"(c[1]), "+f"(c[2]), "+f"(c[3])
                 : "r"(a[0]), "r"(a[1]), "r"(a[2]), "r"(a[3]), "r"(b[0]), "r"(b[1]));
}

// A fragments: 4 ldsm.x4 (16-row step -> +2048, XOR bits unchanged since 16%8==0)
__device__ __forceinline__ void load_a4(uint32_t f[4][4], uint32_t base, uint32_t offb) {
    #pragma unroll
    for (int mt = 0; mt < 4; mt++)
        ldsm4(f[mt][0], f[mt][1], f[mt][2], f[mt][3], base + offb + (uint32_t)(mt * 2048));
}
__device__ __forceinline__ void load_b2(uint32_t f[4][2], uint32_t base, uint32_t offb) {
    uint32_t r0, r1, r2, r3;
    ldsm4(r0, r1, r2, r3, base + offb);
    f[0][0] = r0; f[0][1] = r1; f[1][0] = r2; f[1][1] = r3;
    ldsm4(r0, r1, r2, r3, base + offb + 2048);          // +16 rows
    f[2][0] = r0; f[2][1] = r1; f[3][0] = r2; f[3][1] = r3;
}
__device__ __forceinline__ void mma_tile(float acc[4][4][4], uint32_t A[4][4], uint32_t B[4][2]) {
    #pragma unroll
    for (int mt = 0; mt < 4; mt++)
        #pragma unroll
        for (int nt = 0; nt < 4; nt++)
            mma16816(acc[mt][nt], A[mt], B[nt]);
}

// 8 cp16 from 2 per-thread pointers (4 row-groups of 32 rows each per tile).
__device__ __forceinline__ void issue_stage(uint32_t sbase,
    const __half* gA, const __half* gB, int K32, uint32_t so0)
{
    #pragma unroll
    for (int i = 0; i < 4; i++) {
        cp16(sbase + so0 + (uint32_t)(i * 4096),          gA + i * K32);
        cp16(sbase + TILE_B + so0 + (uint32_t)(i * 4096), gB + i * K32);
    }
}

// Epilogue MODE:
//  0: u = acc+bias0 -> oh (fp16, width HH) ; gate = sigmoid(acc+bias1) -> oh2 (fp16, width HH)
//  1/3: out0 = res + acc + bias0 (fp32)
//  2: silu(acc+bias0) -> oh (fp16, width H2)
template <int MODE>
__device__ __forceinline__ void epi_pair(int r, int c, float v0, float v1,
    const float* __restrict__ bias0, const float* __restrict__ bias1,
    const float* __restrict__ res, float* __restrict__ out0,
    __half* __restrict__ oh, __half* __restrict__ oh2)
{
    size_t mg = (size_t)r;
    if (MODE == 0) {
        if (c < HH) {
            __half2 p;
            p.x = __float2half(v0 + bias0[c]);
            p.y = __float2half(v1 + bias0[c+1]);
            *reinterpret_cast<__half2*>(oh + mg*HH + c) = p;
        } else {
            int cc = c - HH;
            __half2 p;
            p.x = __float2half(sigm(v0 + bias1[cc]));
            p.y = __float2half(sigm(v1 + bias1[cc+1]));
            *reinterpret_cast<__half2*>(oh2 + mg*HH + cc) = p;
        }
    } else if (MODE == 1 || MODE == 3) {
        float2 rr = *reinterpret_cast<const float2*>(res + mg*HH + c);
        float2 o = make_float2(rr.x + v0 + bias0[c], rr.y + v1 + bias0[c+1]);
        *reinterpret_cast<float2*>(out0 + mg*HH + c) = o;
    } else { // MODE 2
        float t0 = v0 + bias0[c], t1 = v1 + bias0[c+1];
        __half2 p;
        p.x = __float2half(t0 * sigm(t0));
        p.y = __float2half(t1 * sigm(t1));
        *reinterpret_cast<__half2*>(oh + mg*H2 + c) = p;
    }
}

template <int MODE>
__global__ void __launch_bounds__(GTHREADS, 2) gemm_fp16_kernel(
    const __half* __restrict__ A, int K,
    const __half* __restrict__ B,
    const float* __restrict__ bias0, const float* __restrict__ bias1,
    const float* __restrict__ res, float* __restrict__ out0,
    __half* __restrict__ oh, __half* __restrict__ oh2)
{
    extern __shared__ char smem[];
    uint32_t sb = smem_u32(smem);
    const int tid = threadIdx.x, wid = tid >> 5, lid = tid & 31;
    const int m0 = blockIdx.y * 128, n0 = blockIdx.x * 128;   // x = n-tile (L2 A-reuse)
    const int wr = wid >> 2, wc = wid & 3;       // warp tile: rows wr*64, cols wc*32
    const int nk = K >> 6;
    const int K32 = K * 32;

    float acc[4][4][4];
    #pragma unroll
    for (int i = 0; i < 4; i++)
        #pragma unroll
        for (int j = 0; j < 4; j++)
            #pragma unroll
            for (int q = 0; q < 4; q++) acc[i][j][q] = 0.f;

    // per-kt fragment read offsets (kt = 0..3, chunk = kt*2 + ch)
    const int rowA = wr*64 + ((lid >> 3) & 1) * 8 + (lid & 7);
    const int chA  = (lid >> 4);
    const int rowB = wc*32 + (lid >> 4) * 8 + (lid & 7);
    const int chB  = ((lid >> 3) & 1);
    uint32_t offA[4], offB[4];
    #pragma unroll
    for (int kt = 0; kt < 4; kt++) {
        offA[kt] = sw_off(rowA, kt*2 + chA);
        offB[kt] = sw_off(rowB, kt*2 + chB);
    }

    // per-thread cp.async pointers (advance 64 elements/chunk)
    const int rowS = tid >> 3, cS = tid & 7;     // 32 rows x 8 chunks per pass
    const uint32_t so0 = sw_off(rowS, cS);
    const __half* gA = A + (size_t)(m0 + rowS) * K + cS * 8;
    const __half* gB = B + (size_t)(n0 + rowS) * K + cS * 8;

    #pragma unroll
    for (int s = 0; s < GSTAGES - 1; s++) {
        issue_stage(sb + s*STAGE_B, gA, gB, K32, so0);
        gA += BKK; gB += BKK;
        CP_COMMIT();
    }

    uint32_t A0[4][4], A1[4][4], B0[4][2], B1[4][2];
    // preload entry fragments of chunk 0 (stage 0 complete after wait(1)+barrier)
    CP_WAIT(1);
    __syncthreads();
    load_a4(A0, sb, offA[0]);
    load_b2(B0, sb + TILE_B, offB[0]);

    for (int kc = 0; kc < nk; kc++) {
        CP_WAIT(0);                 // slots kc AND kc+1 data complete
        __syncthreads();            // ... and visible to all warps
        uint32_t st = sb + (uint32_t)(kc % GSTAGES) * STAGE_B;

        if (kc + GSTAGES - 1 < nk) {
            issue_stage(sb + (uint32_t)((kc + GSTAGES - 1) % GSTAGES) * STAGE_B,
                        gA, gB, K32, so0);
            gA += BKK; gB += BKK;
        }
        CP_COMMIT();

        // fully staggered: every load batch covered by an MMA phase; entry of
        // next chunk preloaded under kt2/kt3.
        load_a4(A1, st, offA[1]);
        load_b2(B1, st + TILE_B, offB[1]);
        mma_tile(acc, A0, B0);                       // kt0
        load_a4(A0, st, offA[2]);
        load_b2(B0, st + TILE_B, offB[2]);
        mma_tile(acc, A1, B1);                       // kt1
        load_a4(A1, st, offA[3]);
        load_b2(B1, st + TILE_B, offB[3]);
        mma_tile(acc, A0, B0);                       // kt2
        if (kc + 1 < nk) {
            uint32_t stn = sb + (uint32_t)((kc + 1) % GSTAGES) * STAGE_B;
            load_a4(A0, stn, offA[0]);               // entry of kc+1
            load_b2(B0, stn + TILE_B, offB[0]);
        }
        mma_tile(acc, A1, B1);                       // kt3
    }

    #pragma unroll
    for (int mt = 0; mt < 4; mt++)
        #pragma unroll
        for (int nt = 0; nt < 4; nt++) {
            float* a4 = acc[mt][nt];
            int r = m0 + wr*64 + mt*16 + (lid >> 2);
            int c = n0 + wc*32 + nt*8 + ((lid & 3) << 1);
            epi_pair<MODE>(r,     c, a4[0], a4[1], bias0, bias1, res, out0, oh, oh2);
            epi_pair<MODE>(r + 8, c, a4[2], a4[3], bias0, bias1, res, out0, oh, oh2);
        }
}

// ===================== host =====================

extern "C" void kernel_launch(void* const* d_in, const int* in_sizes, int n_in,
                              void* d_out, int out_size) {
    const float* x        = (const float*)d_in[0];
    const float* ln1_w    = (const float*)d_in[1];
    const float* ln1_b    = (const float*)d_in[2];
    const float* W_in     = (const float*)d_in[3];
    const float* b_in     = (const float*)d_in[4];
    const float* W_gate   = (const float*)d_in[5];
    const float* b_gate   = (const float*)d_in[6];
    const float* W_out    = (const float*)d_in[7];
    const float* b_out    = (const float*)d_in[8];
    const float* sdecay   = (const float*)d_in[9];
    const float* ln2_w    = (const float*)d_in[10];
    const float* ln2_b    = (const float*)d_in[11];
    const float* W_ff1    = (const float*)d_in[12];
    const float* b_ff1    = (const float*)d_in[13];
    const float* W_ff2    = (const float*)d_in[14];
    const float* b_ff2    = (const float*)d_in[15];
    float* out = (float*)d_out;

    void *p_hid, *p_u, *p_gate, *p_st, *p_y, *p_h2, *p_ff1;
    void *p_Wug, *p_Wout, *p_Wff1, *p_Wff2;
    void *p_cf, *p_cb, *p_sinf, *p_sinb;
    cudaGetSymbolAddress(&p_hid, g_hid);
    cudaGetSymbolAddress(&p_u, g_u);        cudaGetSymbolAddress(&p_gate, g_gate);
    cudaGetSymbolAddress(&p_st, g_st);      cudaGetSymbolAddress(&p_y, g_y);
    cudaGetSymbolAddress(&p_h2, g_h2);      cudaGetSymbolAddress(&p_ff1, g_ff1);
    cudaGetSymbolAddress(&p_Wug, g_Wug);    cudaGetSymbolAddress(&p_Wout, g_Wout);
    cudaGetSymbolAddress(&p_Wff1, g_Wff1);  cudaGetSymbolAddress(&p_Wff2, g_Wff2);
    cudaGetSymbolAddress(&p_cf, g_cf);      cudaGetSymbolAddress(&p_cb, g_cb);
    cudaGetSymbolAddress(&p_sinf, g_sinf);  cudaGetSymbolAddress(&p_sinb, g_sinb);

    cudaFuncSetAttribute(gemm_fp16_kernel<0>, cudaFuncAttributeMaxDynamicSharedMemorySize, GSMEM_BYTES);
    cudaFuncSetAttribute(gemm_fp16_kernel<1>, cudaFuncAttributeMaxDynamicSharedMemorySize, GSMEM_BYTES);
    cudaFuncSetAttribute(gemm_fp16_kernel<2>, cudaFuncAttributeMaxDynamicSharedMemorySize, GSMEM_BYTES);
    cudaFuncSetAttribute(gemm_fp16_kernel<3>, cudaFuncAttributeMaxDynamicSharedMemorySize, GSMEM_BYTES);

    __half* hid  = (__half*)p_hid;
    __half* u16  = (__half*)p_u;
    __half* gate = (__half*)p_gate;
    __half* st   = (__half*)p_st;
    __half* h2   = (__half*)p_h2;
    __half* ff1  = (__half*)p_ff1;
    __half* Wug  = (__half*)p_Wug;
    __half* Wout = (__half*)p_Wout;
    __half* Wff1 = (__half*)p_Wff1;
    __half* Wff2 = (__half*)p_Wff2;

    // weight transposes for G1 (Wug holds W_in rows [0,HH) and W_gate rows [HH,2HH))
    transpose_h_kernel<<<dim3(HH/32, HH/64), 256>>>(W_in,  Wug, HH, HH);
    transpose_h_kernel<<<dim3(HH/32, HH/64), 256>>>(W_gate, Wug + (size_t)HH*HH, HH, HH);
    // LN1 -> hidden (fp16)
    ln_h_kernel<<<LL, 256>>>(x, ln1_w, ln1_b, hid);

    // G1 fused u/gate (N = 2048), u and gate stored fp16
    gemm_fp16_kernel<0><<<dim3(H2/128, LL/128), GTHREADS, GSMEM_BYTES>>>(
        hid, HH, Wug,
        b_in, b_gate, nullptr, nullptr, u16, gate);

    // remaining weight transposes
    transpose_h_kernel<<<dim3(HH/32, HH/64), 256>>>(W_out, Wout, HH, HH);
    transpose_h_kernel<<<dim3(H2/32, HH/64), 256>>>(W_ff1, Wff1, HH, H2);
    transpose_h_kernel<<<dim3(HH/32, H2/64), 256>>>(W_ff2, Wff2, H2, HH);

    // scan
    scan_p1_kernel<<<dim3(GG, HH/128), 128>>>(
        u16, sdecay, (float*)p_cf, (float*)p_cb);
    scan_p2_kernel<<<dim3(HH/256, 2), 256>>>(
        (const float*)p_cf, (const float*)p_cb, sdecay, (float*)p_sinf, (float*)p_sinb);
    scan_p3_kernel<<<dim3(GG, HH/128), 128>>>(
        u16, gate, sdecay,
        (const float*)p_sinf, (const float*)p_sinb, st);

    // G2: y = x + state@W_out + b_out
    gemm_fp16_kernel<1><<<dim3(HH/128, LL/128), GTHREADS, GSMEM_BYTES>>>(
        st, HH, Wout,
        b_out, nullptr, x, (float*)p_y, nullptr, nullptr);

    // LN2 -> h (fp16)
    ln_h_kernel<<<LL, 256>>>((const float*)p_y, ln2_w, ln2_b, h2);

    // G3: ff1 = silu(h@W_ff1 + b_ff1) -> fp16 (N = 2048)
    gemm_fp16_kernel<2><<<dim3(H2/128, LL/128), GTHREADS, GSMEM_BYTES>>>(
        h2, HH, Wff1,
        b_ff1, nullptr, nullptr, nullptr, ff1, nullptr);

    // G4: out = y + ff1@W_ff2 + b_ff2  (K = 2048)
    gemm_fp16_kernel<3><<<dim3(HH/128, LL/128), GTHREADS, GSMEM_BYTES>>>(
        ff1, H2, Wff2,
        b_ff2, nullptr, (const float*)p_y, out, nullptr, nullptr);
}

// round 16
// speedup vs baseline: 1.0993x; 1.0993x over previous
#include <cuda_runtime.h>
#include <cuda_fp16.h>
#include <cstdint>

// ===================== sizes =====================
#define LL 16384
#define HH 1024
#define H2 2048
#define CCH 32           // scan chunk length (register-resident)
#define GG  (LL/CCH)     // 512 chunks
#define EPS 1e-5f

__device__ __forceinline__ float sigm(float z) { return 1.f / (1.f + expf(-z)); }

// ===================== device scratch (everything fp16 except y) ================
__device__ __half g_hid [(size_t)LL*HH];
__device__ __half g_u   [(size_t)LL*HH];
__device__ __half g_gate[(size_t)LL*HH];
__device__ __half g_st  [(size_t)LL*HH];
__device__ float  g_y[(size_t)LL*HH];
__device__ __half g_h2  [(size_t)LL*HH];
__device__ __half g_ff1 [(size_t)LL*H2];
__device__ __half g_Wug [(size_t)H2*HH];
__device__ __half g_Wout[(size_t)HH*HH];
__device__ __half g_Wff1[(size_t)H2*HH];
__device__ __half g_Wff2[(size_t)HH*H2];
__device__ float g_cf[GG*HH], g_cb[GG*HH], g_sinf[GG*HH], g_sinb[GG*HH];

// ===================== small kernels =====================

// Batched transpose+convert: ALL 5 weights in one launch.
// blockIdx.z selects matrix; per-matrix tile grid (N/32, K/64); oversized blocks exit.
// src [K,N] fp32 -> dst [N,K] fp16.
__device__ __forceinline__ void transpose_tile(const float* __restrict__ src,
                                               __half* __restrict__ dh, int K, int N) {
    __shared__ float tile[64][33];
    int kb = blockIdx.y * 64, nb = blockIdx.x * 32;
    int tid = threadIdx.x;
    int tn = tid & 31, tk = tid >> 5;       // 8 k-rows, step 8
    #pragma unroll
    for (int i = 0; i < 8; i++)
        tile[tk + i*8][tn] = src[(size_t)(kb + tk + i*8) * N + nb + tn];
    __syncthreads();
    int on = tid >> 3, oj = tid & 7;        // 32 n-rows, 8 k-pair slots
    #pragma unroll
    for (int i = 0; i < 4; i++) {
        int kp = (oj + i*8) * 2;
        __half2 v;
        v.x = __float2half(tile[kp][on]);
        v.y = __float2half(tile[kp+1][on]);
        *reinterpret_cast<__half2*>(dh + (size_t)(nb + on) * K + kb + kp) = v;
    }
}

__global__ void transpose_all_kernel(const float* __restrict__ Win,
                                     const float* __restrict__ Wgate,
                                     const float* __restrict__ Wout,
                                     const float* __restrict__ Wff1,
                                     const float* __restrict__ Wff2,
                                     __half* __restrict__ dWug,
                                     __half* __restrict__ dWout,
                                     __half* __restrict__ dWff1,
                                     __half* __restrict__ dWff2) {
    switch (blockIdx.z) {
    case 0:  // W_in [HH,HH] -> Wug rows [0,HH)
        if (blockIdx.x < HH/32 && blockIdx.y < HH/64)
            transpose_tile(Win, dWug, HH, HH);
        break;
    case 1:  // W_gate [HH,HH] -> Wug rows [HH,2HH)
        if (blockIdx.x < HH/32 && blockIdx.y < HH/64)
            transpose_tile(Wgate, dWug + (size_t)HH*HH, HH, HH);
        break;
    case 2:  // W_out [HH,HH]
        if (blockIdx.x < HH/32 && blockIdx.y < HH/64)
            transpose_tile(Wout, dWout, HH, HH);
        break;
    case 3:  // W_ff1 [HH,H2]
        if (blockIdx.x < H2/32 && blockIdx.y < HH/64)
            transpose_tile(Wff1, dWff1, HH, H2);
        break;
    default: // W_ff2 [H2,HH]
        if (blockIdx.x < HH/32 && blockIdx.y < H2/64)
            transpose_tile(Wff2, dWff2, H2, HH);
        break;
    }
}

// LayerNorm -> fp16. block = 256 threads, one row per block.
__global__ void ln_h_kernel(const float* __restrict__ x, const float* __restrict__ w,
                            const float* __restrict__ b, __half* __restrict__ oh) {
    __shared__ float red[8];
    int row = blockIdx.x, tid = threadIdx.x;
    const float* xr = x + (size_t)row * HH;
    float v[4];
    float s = 0.f;
    #pragma unroll
    for (int i = 0; i < 4; i++) { v[i] = xr[tid + i*256]; s += v[i]; }
    #pragma unroll
    for (int o = 16; o; o >>= 1) s += __shfl_xor_sync(0xffffffffu, s, o);
    if ((tid & 31) == 0) red[tid >> 5] = s;
    __syncthreads();
    float tot = 0.f;
    #pragma unroll
    for (int i = 0; i < 8; i++) tot += red[i];
    float mean = tot * (1.f / HH);
    __syncthreads();
    float vs = 0.f;
    #pragma unroll
    for (int i = 0; i < 4; i++) { float d = v[i] - mean; vs += d * d; }
    #pragma unroll
    for (int o = 16; o; o >>= 1) vs += __shfl_xor_sync(0xffffffffu, vs, o);
    if ((tid & 31) == 0) red[tid >> 5] = vs;
    __syncthreads();
    float var = 0.f;
    #pragma unroll
    for (int i = 0; i < 8; i++) var += red[i];
    var *= (1.f / HH);
    float rstd = rsqrtf(var + EPS);
    #pragma unroll
    for (int i = 0; i < 4; i++) {
        int idx = tid + i*256;
        float val = (v[i] - mean) * rstd * w[idx] + b[idx];
        oh[(size_t)row * HH + idx] = __float2half(val);
    }
}

// scan pass1: per-chunk carries, u (fp16) register-resident. grid (GG, HH/128), block 128.
__global__ void scan_p1_kernel(const __half* __restrict__ u, const float* __restrict__ sd,
                               float* __restrict__ cf, float* __restrict__ cb) {
    int g = blockIdx.x;
    int c = blockIdx.y * 128 + threadIdx.x;
    float d = sigm(sd[c]);
    const __half* up = u + (size_t)g * CCH * HH + c;
    float vv[CCH];
    #pragma unroll
    for (int t = 0; t < CCH; t++) vv[t] = __half2float(up[(size_t)t * HH]);
    float sf = 0.f, sb = 0.f;
    #pragma unroll
    for (int t = 0; t < CCH; t++) sf = d * sf + vv[t];
    #pragma unroll
    for (int t = CCH - 1; t >= 0; t--) sb = d * sb + vv[t];
    cf[g*HH + c] = sf;
    cb[g*HH + c] = sb;
}

// scan pass2: cross-chunk exclusive scan; blockIdx.y = direction. grid (HH/256, 2), block 256.
__global__ void scan_p2_kernel(const float* __restrict__ cf, const float* __restrict__ cb,
                               const float* __restrict__ sd,
                               float* __restrict__ sinf, float* __restrict__ sinb) {
    int c = blockIdx.x * 256 + threadIdx.x;
    float d = sigm(sd[c]);
    float dC = d;
    #pragma unroll
    for (int i = 0; i < 5; i++) dC *= dC;   // d^32
    if (blockIdx.y == 0) {
        float s = 0.f;
        for (int g = 0; g < GG; g++) { sinf[g*HH + c] = s; s = dC * s + cf[g*HH + c]; }
    } else {
        float s = 0.f;
        for (int g = GG - 1; g >= 0; g--) { sinb[g*HH + c] = s; s = dC * s + cb[g*HH + c]; }
    }
}

// scan pass3 (fused fwd+bwd, register-resident): combine + gate -> fp16.
__global__ void scan_p3_kernel(const __half* __restrict__ u, const __half* __restrict__ gate,
                               const float* __restrict__ sd,
                               const float* __restrict__ sinf, const float* __restrict__ sinb,
                               __half* __restrict__ oh) {
    int g = blockIdx.x;
    int c = blockIdx.y * 128 + threadIdx.x;
    float d = sigm(sd[c]);
    size_t base = (size_t)g * CCH * HH + c;
    float vv[CCH], fs[CCH];
    #pragma unroll
    for (int t = 0; t < CCH; t++) vv[t] = __half2float(u[base + (size_t)t * HH]);
    float s = sinf[g*HH + c];
    #pragma unroll
    for (int t = 0; t < CCH; t++) { s = d * s + vv[t]; fs[t] = s; }
    float sb = sinb[g*HH + c];
    #pragma unroll
    for (int t = CCH - 1; t >= 0; t--) {
        size_t o = base + (size_t)t * HH;
        sb = d * sb + vv[t];
        float so = 0.5f * (fs[t] + sb) * __half2float(gate[o]);
        oh[o] = __float2half(so);
    }
}

// ===================== GEMM (plain fp16, mma.sync + cp.async) — R14 frozen ========
// C[M,N] = A[M,K] * B^T  (B stored [N,K]), fp32 accumulate.
// BM=128, BN=128, BK=64, 256 threads (8 warps 2x4, warp tile 64x32), 3-stage cp.async.
#define BKK 64
#define GSTAGES 3
#define GTHREADS 256
#define TILE_B 16384                // 128 rows x 64 cols x 2B
#define STAGE_B (2*TILE_B)          // A, B = 32768
#define GSMEM_BYTES (GSTAGES*STAGE_B)   // 98304

// SW128: 128B rows, 8 x 16B chunks, chunk ^= row&7
__device__ __forceinline__ uint32_t sw_off(int row, int chunk) {
    return (uint32_t)(row * 128 + (((chunk ^ row) & 7) << 4));
}
__device__ __forceinline__ uint32_t smem_u32(const void* p) {
    uint32_t a;
    asm("{ .reg .u64 t; cvta.to.shared.u64 t, %1; cvt.u32.u64 %0, t; }" : "=r"(a) : "l"(p));
    return a;
}
__device__ __forceinline__ void cp16(uint32_t saddr, const void* gaddr) {
    asm volatile("cp.async.cg.shared.global [%0], [%1], 16;" :: "r"(saddr), "l"(gaddr));
}
#define CP_COMMIT() asm volatile("cp.async.commit_group;" ::: "memory")
#define CP_WAIT(n)  asm volatile("cp.async.wait_group %0;" :: "n"(n) : "memory")

__device__ __forceinline__ void ldsm4(uint32_t& r0, uint32_t& r1, uint32_t& r2, uint32_t& r3,
                                      uint32_t addr) {
    asm volatile("ldmatrix.sync.aligned.m8n8.x4.shared.b16 {%0,%1,%2,%3}, [%4];"
                 : "=r"(r0), "=r"(r1), "=r"(r2), "=r"(r3) : "r"(addr));
}
__device__ __forceinline__ void mma16816(float* c, const uint32_t* a, const uint32_t* b) {
    asm volatile("mma.sync.aligned.m16n8k16.row.col.f32.f16.f16.f32 "
                 "{%0,%1,%2,%3}, {%4,%5,%6,%7}, {%8,%9}, {%0,%1,%2,%3};"
                 : "+f"(c[0]), "+f"(c[1]), "+f"(c[2]), "+f"(c[3])
                 : "r"(a[0]), "r"(a[1]), "r"(a[2]), "r"(a[3]), "r"(b[0]), "r"(b[1]));
}

// A fragments: 4 ldsm.x4 (16-row step -> +2048, XOR bits unchanged since 16%8==0)
__device__ __forceinline__ void load_a4(uint32_t f[4][4], uint32_t base, uint32_t offb) {
    #pragma unroll
    for (int mt = 0; mt < 4; mt++)
        ldsm4(f[mt][0], f[mt][1], f[mt][2], f[mt][3], base + offb + (uint32_t)(mt * 2048));
}
__device__ __forceinline__ void load_b2(uint32_t f[4][2], uint32_t base, uint32_t offb) {
    uint32_t r0, r1, r2, r3;
    ldsm4(r0, r1, r2, r3, base + offb);
    f[0][0] = r0; f[0][1] = r1; f[1][0] = r2; f[1][1] = r3;
    ldsm4(r0, r1, r2, r3, base + offb + 2048);          // +16 rows
    f[2][0] = r0; f[2][1] = r1; f[3][0] = r2; f[3][1] = r3;
}
__device__ __forceinline__ void mma_tile(float acc[4][4][4], uint32_t A[4][4], uint32_t B[4][2]) {
    #pragma unroll
    for (int mt = 0; mt < 4; mt++)
        #pragma unroll
        for (int nt = 0; nt < 4; nt++)
            mma16816(acc[mt][nt], A[mt], B[nt]);
}

// 8 cp16 from 2 per-thread pointers (4 row-groups of 32 rows each per tile).
__device__ __forceinline__ void issue_stage(uint32_t sbase,
    const __half* gA, const __half* gB, int K32, uint32_t so0)
{
    #pragma unroll
    for (int i = 0; i < 4; i++) {
        cp16(sbase + so0 + (uint32_t)(i * 4096),          gA + i * K32);
        cp16(sbase + TILE_B + so0 + (uint32_t)(i * 4096), gB + i * K32);
    }
}

// Epilogue MODE:
//  0: u = acc+bias0 -> oh (fp16, width HH) ; gate = sigmoid(acc+bias1) -> oh2 (fp16, width HH)
//  1/3: out0 = res + acc + bias0 (fp32)
//  2: silu(acc+bias0) -> oh (fp16, width H2)
template <int MODE>
__device__ __forceinline__ void epi_pair(int r, int c, float v0, float v1,
    const float* __restrict__ bias0, const float* __restrict__ bias1,
    const float* __restrict__ res, float* __restrict__ out0,
    __half* __restrict__ oh, __half* __restrict__ oh2)
{
    size_t mg = (size_t)r;
    if (MODE == 0) {
        if (c < HH) {
            __half2 p;
            p.x = __float2half(v0 + bias0[c]);
            p.y = __float2half(v1 + bias0[c+1]);
            *reinterpret_cast<__half2*>(oh + mg*HH + c) = p;
        } else {
            int cc = c - HH;
            __half2 p;
            p.x = __float2half(sigm(v0 + bias1[cc]));
            p.y = __float2half(sigm(v1 + bias1[cc+1]));
            *reinterpret_cast<__half2*>(oh2 + mg*HH + cc) = p;
        }
    } else if (MODE == 1 || MODE == 3) {
        float2 rr = *reinterpret_cast<const float2*>(res + mg*HH + c);
        float2 o = make_float2(rr.x + v0 + bias0[c], rr.y + v1 + bias0[c+1]);
        *reinterpret_cast<float2*>(out0 + mg*HH + c) = o;
    } else { // MODE 2
        float t0 = v0 + bias0[c], t1 = v1 + bias0[c+1];
        __half2 p;
        p.x = __float2half(t0 * sigm(t0));
        p.y = __float2half(t1 * sigm(t1));
        *reinterpret_cast<__half2*>(oh + mg*H2 + c) = p;
    }
}

template <int MODE>
__global__ void __launch_bounds__(GTHREADS, 2) gemm_fp16_kernel(
    const __half* __restrict__ A, int K,
    const __half* __restrict__ B,
    const float* __restrict__ bias0, const float* __restrict__ bias1,
    const float* __restrict__ res, float* __restrict__ out0,
    __half* __restrict__ oh, __half* __restrict__ oh2)
{
    extern __shared__ char smem[];
    uint32_t sb = smem_u32(smem);
    const int tid = threadIdx.x, wid = tid >> 5, lid = tid & 31;
    const int m0 = blockIdx.y * 128, n0 = blockIdx.x * 128;   // x = n-tile (L2 A-reuse)
    const int wr = wid >> 2, wc = wid & 3;       // warp tile: rows wr*64, cols wc*32
    const int nk = K >> 6;
    const int K32 = K * 32;

    float acc[4][4][4];
    #pragma unroll
    for (int i = 0; i < 4; i++)
        #pragma unroll
        for (int j = 0; j < 4; j++)
            #pragma unroll
            for (int q = 0; q < 4; q++) acc[i][j][q] = 0.f;

    // per-kt fragment read offsets (kt = 0..3, chunk = kt*2 + ch)
    const int rowA = wr*64 + ((lid >> 3) & 1) * 8 + (lid & 7);
    const int chA  = (lid >> 4);
    const int rowB = wc*32 + (lid >> 4) * 8 + (lid & 7);
    const int chB  = ((lid >> 3) & 1);
    uint32_t offA[4], offB[4];
    #pragma unroll
    for (int kt = 0; kt < 4; kt++) {
        offA[kt] = sw_off(rowA, kt*2 + chA);
        offB[kt] = sw_off(rowB, kt*2 + chB);
    }

    // per-thread cp.async pointers (advance 64 elements/chunk)
    const int rowS = tid >> 3, cS = tid & 7;     // 32 rows x 8 chunks per pass
    const uint32_t so0 = sw_off(rowS, cS);
    const __half* gA = A + (size_t)(m0 + rowS) * K + cS * 8;
    const __half* gB = B + (size_t)(n0 + rowS) * K + cS * 8;

    #pragma unroll
    for (int s = 0; s < GSTAGES - 1; s++) {
        issue_stage(sb + s*STAGE_B, gA, gB, K32, so0);
        gA += BKK; gB += BKK;
        CP_COMMIT();
    }

    for (int kc = 0; kc < nk; kc++) {
        CP_WAIT(GSTAGES - 2);
        __syncthreads();
        uint32_t st = sb + (uint32_t)(kc % GSTAGES) * STAGE_B;

        uint32_t A0[4][4], A1[4][4], B0[4][2], B1[4][2];
        // entry fragment loads FIRST (latency partly hidden by cp16 issues below)
        load_a4(A0, st, offA[0]);
        load_b2(B0, st + TILE_B, offB[0]);

        if (kc + GSTAGES - 1 < nk) {
            issue_stage(sb + (uint32_t)((kc + GSTAGES - 1) % GSTAGES) * STAGE_B,
                        gA, gB, K32, so0);
            gA += BKK; gB += BKK;
        }
        CP_COMMIT();

        // 4 kt-halves, double-buffered fragments
        load_a4(A1, st, offA[1]);
        load_b2(B1, st + TILE_B, offB[1]);
        mma_tile(acc, A0, B0);                       // kt0
        load_a4(A0, st, offA[2]);
        load_b2(B0, st + TILE_B, offB[2]);
        mma_tile(acc, A1, B1);                       // kt1
        load_a4(A1, st, offA[3]);
        load_b2(B1, st + TILE_B, offB[3]);
        mma_tile(acc, A0, B0);                       // kt2
        mma_tile(acc, A1, B1);                       // kt3
    }

    #pragma unroll
    for (int mt = 0; mt < 4; mt++)
        #pragma unroll
        for (int nt = 0; nt < 4; nt++) {
            float* a4 = acc[mt][nt];
            int r = m0 + wr*64 + mt*16 + (lid >> 2);
            int c = n0 + wc*32 + nt*8 + ((lid & 3) << 1);
            epi_pair<MODE>(r,     c, a4[0], a4[1], bias0, bias1, res, out0, oh, oh2);
            epi_pair<MODE>(r + 8, c, a4[2], a4[3], bias0, bias1, res, out0, oh, oh2);
        }
}

// ===================== host =====================

extern "C" void kernel_launch(void* const* d_in, const int* in_sizes, int n_in,
                              void* d_out, int out_size) {
    const float* x        = (const float*)d_in[0];
    const float* ln1_w    = (const float*)d_in[1];
    const float* ln1_b    = (const float*)d_in[2];
    const float* W_in     = (const float*)d_in[3];
    const float* b_in     = (const float*)d_in[4];
    const float* W_gate   = (const float*)d_in[5];
    const float* b_gate   = (const float*)d_in[6];
    const float* W_out    = (const float*)d_in[7];
    const float* b_out    = (const float*)d_in[8];
    const float* sdecay   = (const float*)d_in[9];
    const float* ln2_w    = (const float*)d_in[10];
    const float* ln2_b    = (const float*)d_in[11];
    const float* W_ff1    = (const float*)d_in[12];
    const float* b_ff1    = (const float*)d_in[13];
    const float* W_ff2    = (const float*)d_in[14];
    const float* b_ff2    = (const float*)d_in[15];
    float* out = (float*)d_out;

    void *p_hid, *p_u, *p_gate, *p_st, *p_y, *p_h2, *p_ff1;
    void *p_Wug, *p_Wout, *p_Wff1, *p_Wff2;
    void *p_cf, *p_cb, *p_sinf, *p_sinb;
    cudaGetSymbolAddress(&p_hid, g_hid);
    cudaGetSymbolAddress(&p_u, g_u);        cudaGetSymbolAddress(&p_gate, g_gate);
    cudaGetSymbolAddress(&p_st, g_st);      cudaGetSymbolAddress(&p_y, g_y);
    cudaGetSymbolAddress(&p_h2, g_h2);      cudaGetSymbolAddress(&p_ff1, g_ff1);
    cudaGetSymbolAddress(&p_Wug, g_Wug);    cudaGetSymbolAddress(&p_Wout, g_Wout);
    cudaGetSymbolAddress(&p_Wff1, g_Wff1);  cudaGetSymbolAddress(&p_Wff2, g_Wff2);
    cudaGetSymbolAddress(&p_cf, g_cf);      cudaGetSymbolAddress(&p_cb, g_cb);
    cudaGetSymbolAddress(&p_sinf, g_sinf);  cudaGetSymbolAddress(&p_sinb, g_sinb);

    cudaFuncSetAttribute(gemm_fp16_kernel<0>, cudaFuncAttributeMaxDynamicSharedMemorySize, GSMEM_BYTES);
    cudaFuncSetAttribute(gemm_fp16_kernel<1>, cudaFuncAttributeMaxDynamicSharedMemorySize, GSMEM_BYTES);
    cudaFuncSetAttribute(gemm_fp16_kernel<2>, cudaFuncAttributeMaxDynamicSharedMemorySize, GSMEM_BYTES);
    cudaFuncSetAttribute(gemm_fp16_kernel<3>, cudaFuncAttributeMaxDynamicSharedMemorySize, GSMEM_BYTES);

    __half* hid  = (__half*)p_hid;
    __half* u16  = (__half*)p_u;
    __half* gate = (__half*)p_gate;
    __half* st   = (__half*)p_st;
    __half* h2   = (__half*)p_h2;
    __half* ff1  = (__half*)p_ff1;
    __half* Wug  = (__half*)p_Wug;
    __half* Wout = (__half*)p_Wout;
    __half* Wff1 = (__half*)p_Wff1;
    __half* Wff2 = (__half*)p_Wff2;

    // ALL weight transposes in one launch (z selects matrix; oversize blocks exit)
    transpose_all_kernel<<<dim3(H2/32, H2/64, 5), 256>>>(
        W_in, W_gate, W_out, W_ff1, W_ff2, Wug, Wout, Wff1, Wff2);

    // LN1 -> hidden (fp16)
    ln_h_kernel<<<LL, 256>>>(x, ln1_w, ln1_b, hid);

    // G1 fused u/gate (N = 2048), u and gate stored fp16
    gemm_fp16_kernel<0><<<dim3(H2/128, LL/128), GTHREADS, GSMEM_BYTES>>>(
        hid, HH, Wug,
        b_in, b_gate, nullptr, nullptr, u16, gate);

    // scan
    scan_p1_kernel<<<dim3(GG, HH/128), 128>>>(
        u16, sdecay, (float*)p_cf, (float*)p_cb);
    scan_p2_kernel<<<dim3(HH/256, 2), 256>>>(
        (const float*)p_cf, (const float*)p_cb, sdecay, (float*)p_sinf, (float*)p_sinb);
    scan_p3_kernel<<<dim3(GG, HH/128), 128>>>(
        u16, gate, sdecay,
        (const float*)p_sinf, (const float*)p_sinb, st);

    // G2: y = x + state@W_out + b_out
    gemm_fp16_kernel<1><<<dim3(HH/128, LL/128), GTHREADS, GSMEM_BYTES>>>(
        st, HH, Wout,
        b_out, nullptr, x, (float*)p_y, nullptr, nullptr);

    // LN2 -> h (fp16)
    ln_h_kernel<<<LL, 256>>>((const float*)p_y, ln2_w, ln2_b, h2);

    // G3: ff1 = silu(h@W_ff1 + b_ff1) -> fp16 (N = 2048)
    gemm_fp16_kernel<2><<<dim3(H2/128, LL/128), GTHREADS, GSMEM_BYTES>>>(
        h2, HH, Wff1,
        b_ff1, nullptr, nullptr, nullptr, ff1, nullptr);

    // G4: out = y + ff1@W_ff2 + b_ff2  (K = 2048)
    gemm_fp16_kernel<3><<<dim3(HH/128, LL/128), GTHREADS, GSMEM_BYTES>>>(
        ff1, H2, Wff2,
        b_ff2, nullptr, (const float*)p_y, out, nullptr, nullptr);
}

// round 17
// speedup vs baseline: 1.1190x; 1.0179x over previous
#include <cuda_runtime.h>
#include <cuda_fp16.h>
#include <cstdint>

// ===================== sizes =====================
#define LL 16384
#define HH 1024
#define HH2 (HH/2)
#define H2 2048
#define CCH 32           // scan chunk length (register-resident)
#define GG  (LL/CCH)     // 512 chunks
#define EPS 1e-5f

__device__ __forceinline__ float sigm(float z) { return 1.f / (1.f + expf(-z)); }

// ===================== device scratch (everything fp16 except y) ================
__device__ __half g_hid [(size_t)LL*HH];
__device__ __half g_u   [(size_t)LL*HH];
__device__ __half g_gate[(size_t)LL*HH];
__device__ __half g_st  [(size_t)LL*HH];
__device__ float  g_y[(size_t)LL*HH];
__device__ __half g_h2  [(size_t)LL*HH];
__device__ __half g_ff1 [(size_t)LL*H2];
__device__ __half g_Wug [(size_t)H2*HH];
__device__ __half g_Wout[(size_t)HH*HH];
__device__ __half g_Wff1[(size_t)H2*HH];
__device__ __half g_Wff2[(size_t)HH*H2];
__device__ float g_cf[GG*HH], g_cb[GG*HH], g_sinf[GG*HH], g_sinb[GG*HH];

// ===================== small kernels =====================

// Batched transpose+convert: ALL 5 weights in one launch.
__device__ __forceinline__ void transpose_tile(const float* __restrict__ src,
                                               __half* __restrict__ dh, int K, int N) {
    __shared__ float tile[64][33];
    int kb = blockIdx.y * 64, nb = blockIdx.x * 32;
    int tid = threadIdx.x;
    int tn = tid & 31, tk = tid >> 5;       // 8 k-rows, step 8
    #pragma unroll
    for (int i = 0; i < 8; i++)
        tile[tk + i*8][tn] = src[(size_t)(kb + tk + i*8) * N + nb + tn];
    __syncthreads();
    int on = tid >> 3, oj = tid & 7;        // 32 n-rows, 8 k-pair slots
    #pragma unroll
    for (int i = 0; i < 4; i++) {
        int kp = (oj + i*8) * 2;
        __half2 v;
        v.x = __float2half(tile[kp][on]);
        v.y = __float2half(tile[kp+1][on]);
        *reinterpret_cast<__half2*>(dh + (size_t)(nb + on) * K + kb + kp) = v;
    }
}

__global__ void transpose_all_kernel(const float* __restrict__ Win,
                                     const float* __restrict__ Wgate,
                                     const float* __restrict__ Wout,
                                     const float* __restrict__ Wff1,
                                     const float* __restrict__ Wff2,
                                     __half* __restrict__ dWug,
                                     __half* __restrict__ dWout,
                                     __half* __restrict__ dWff1,
                                     __half* __restrict__ dWff2) {
    switch (blockIdx.z) {
    case 0:
        if (blockIdx.x < HH/32 && blockIdx.y < HH/64)
            transpose_tile(Win, dWug, HH, HH);
        break;
    case 1:
        if (blockIdx.x < HH/32 && blockIdx.y < HH/64)
            transpose_tile(Wgate, dWug + (size_t)HH*HH, HH, HH);
        break;
    case 2:
        if (blockIdx.x < HH/32 && blockIdx.y < HH/64)
            transpose_tile(Wout, dWout, HH, HH);
        break;
    case 3:
        if (blockIdx.x < H2/32 && blockIdx.y < HH/64)
            transpose_tile(Wff1, dWff1, HH, H2);
        break;
    default:
        if (blockIdx.x < HH/32 && blockIdx.y < H2/64)
            transpose_tile(Wff2, dWff2, H2, HH);
        break;
    }
}

// LayerNorm -> fp16. block = 256 threads, one row per block; float4 loads.
__global__ void ln_h_kernel(const float* __restrict__ x, const float* __restrict__ w,
                            const float* __restrict__ b, __half* __restrict__ oh) {
    __shared__ float red[8];
    int row = blockIdx.x, tid = threadIdx.x;
    const float4 v4 = *reinterpret_cast<const float4*>(x + (size_t)row * HH + tid * 4);
    float s = v4.x + v4.y + v4.z + v4.w;
    #pragma unroll
    for (int o = 16; o; o >>= 1) s += __shfl_xor_sync(0xffffffffu, s, o);
    if ((tid & 31) == 0) red[tid >> 5] = s;
    __syncthreads();
    float tot = 0.f;
    #pragma unroll
    for (int i = 0; i < 8; i++) tot += red[i];
    float mean = tot * (1.f / HH);
    __syncthreads();
    float d0 = v4.x - mean, d1 = v4.y - mean, d2 = v4.z - mean, d3 = v4.w - mean;
    float vs = d0*d0 + d1*d1 + d2*d2 + d3*d3;
    #pragma unroll
    for (int o = 16; o; o >>= 1) vs += __shfl_xor_sync(0xffffffffu, vs, o);
    if ((tid & 31) == 0) red[tid >> 5] = vs;
    __syncthreads();
    float var = 0.f;
    #pragma unroll
    for (int i = 0; i < 8; i++) var += red[i];
    var *= (1.f / HH);
    float rstd = rsqrtf(var + EPS);
    const float4 w4 = *reinterpret_cast<const float4*>(w + tid * 4);
    const float4 b4 = *reinterpret_cast<const float4*>(b + tid * 4);
    __half2 p0, p1;
    p0.x = __float2half(d0 * rstd * w4.x + b4.x);
    p0.y = __float2half(d1 * rstd * w4.y + b4.y);
    p1.x = __float2half(d2 * rstd * w4.z + b4.z);
    p1.y = __float2half(d3 * rstd * w4.w + b4.w);
    __half* op = oh + (size_t)row * HH + tid * 4;
    *reinterpret_cast<__half2*>(op)     = p0;
    *reinterpret_cast<__half2*>(op + 2) = p1;
}

// scan pass1 (half2, 2 channels/thread): grid (GG, HH2/128), block 128.
__global__ void scan_p1_kernel(const __half2* __restrict__ u2, const float* __restrict__ sd,
                               float2* __restrict__ cf2, float2* __restrict__ cb2) {
    int g = blockIdx.x;
    int c2 = blockIdx.y * 128 + threadIdx.x;         // half2 channel index
    float d0 = sigm(sd[2*c2]), d1 = sigm(sd[2*c2 + 1]);
    const __half2* up = u2 + (size_t)g * CCH * HH2 + c2;
    float2 vv[CCH];
    #pragma unroll
    for (int t = 0; t < CCH; t++) vv[t] = __half22float2(up[(size_t)t * HH2]);
    float sf0 = 0.f, sf1 = 0.f, sb0 = 0.f, sb1 = 0.f;
    #pragma unroll
    for (int t = 0; t < CCH; t++) { sf0 = d0*sf0 + vv[t].x; sf1 = d1*sf1 + vv[t].y; }
    #pragma unroll
    for (int t = CCH - 1; t >= 0; t--) { sb0 = d0*sb0 + vv[t].x; sb1 = d1*sb1 + vv[t].y; }
    cf2[g*HH2 + c2] = make_float2(sf0, sf1);
    cb2[g*HH2 + c2] = make_float2(sb0, sb1);
}

// scan pass2: cross-chunk exclusive scan; blockIdx.y = direction. grid (HH/256, 2), block 256.
__global__ void scan_p2_kernel(const float* __restrict__ cf, const float* __restrict__ cb,
                               const float* __restrict__ sd,
                               float* __restrict__ sinf, float* __restrict__ sinb) {
    int c = blockIdx.x * 256 + threadIdx.x;
    float d = sigm(sd[c]);
    float dC = d;
    #pragma unroll
    for (int i = 0; i < 5; i++) dC *= dC;   // d^32
    if (blockIdx.y == 0) {
        float s = 0.f;
        for (int g = 0; g < GG; g++) { sinf[g*HH + c] = s; s = dC * s + cf[g*HH + c]; }
    } else {
        float s = 0.f;
        for (int g = GG - 1; g >= 0; g--) { sinb[g*HH + c] = s; s = dC * s + cb[g*HH + c]; }
    }
}

// scan pass3 (half2, 2 channels/thread): combine + gate -> fp16. grid (GG, HH2/128), block 128.
__global__ void scan_p3_kernel(const __half2* __restrict__ u2, const __half2* __restrict__ gate2,
                               const float* __restrict__ sd,
                               const float2* __restrict__ sinf2, const float2* __restrict__ sinb2,
                               __half2* __restrict__ oh2) {
    int g = blockIdx.x;
    int c2 = blockIdx.y * 128 + threadIdx.x;
    float d0 = sigm(sd[2*c2]), d1 = sigm(sd[2*c2 + 1]);
    size_t base = (size_t)g * CCH * HH2 + c2;
    float2 vv[CCH], fs[CCH];
    #pragma unroll
    for (int t = 0; t < CCH; t++) vv[t] = __half22float2(u2[base + (size_t)t * HH2]);
    float2 si = sinf2[g*HH2 + c2];
    float s0 = si.x, s1 = si.y;
    #pragma unroll
    for (int t = 0; t < CCH; t++) {
        s0 = d0*s0 + vv[t].x; s1 = d1*s1 + vv[t].y;
        fs[t] = make_float2(s0, s1);
    }
    float2 sbi = sinb2[g*HH2 + c2];
    float b0 = sbi.x, b1 = sbi.y;
    #pragma unroll
    for (int t = CCH - 1; t >= 0; t--) {
        size_t o = base + (size_t)t * HH2;
        b0 = d0*b0 + vv[t].x; b1 = d1*b1 + vv[t].y;
        float2 gv = __half22float2(gate2[o]);
        __half2 p;
        p.x = __float2half(0.5f * (fs[t].x + b0) * gv.x);
        p.y = __float2half(0.5f * (fs[t].y + b1) * gv.y);
        oh2[o] = p;
    }
}

// ===================== GEMM (plain fp16, mma.sync + cp.async) — R14 frozen ========
#define BKK 64
#define GSTAGES 3
#define GTHREADS 256
#define TILE_B 16384                // 128 rows x 64 cols x 2B
#define STAGE_B (2*TILE_B)          // A, B = 32768
#define GSMEM_BYTES (GSTAGES*STAGE_B)   // 98304

// SW128: 128B rows, 8 x 16B chunks, chunk ^= row&7
__device__ __forceinline__ uint32_t sw_off(int row, int chunk) {
    return (uint32_t)(row * 128 + (((chunk ^ row) & 7) << 4));
}
__device__ __forceinline__ uint32_t smem_u32(const void* p) {
    uint32_t a;
    asm("{ .reg .u64 t; cvta.to.shared.u64 t, %1; cvt.u32.u64 %0, t; }" : "=r"(a) : "l"(p));
    return a;
}
__device__ __forceinline__ void cp16(uint32_t saddr, const void* gaddr) {
    asm volatile("cp.async.cg.shared.global [%0], [%1], 16;" :: "r"(saddr), "l"(gaddr));
}
#define CP_COMMIT() asm volatile("cp.async.commit_group;" ::: "memory")
#define CP_WAIT(n)  asm volatile("cp.async.wait_group %0;" :: "n"(n) : "memory")

__device__ __forceinline__ void ldsm4(uint32_t& r0, uint32_t& r1, uint32_t& r2, uint32_t& r3,
                                      uint32_t addr) {
    asm volatile("ldmatrix.sync.aligned.m8n8.x4.shared.b16 {%0,%1,%2,%3}, [%4];"
                 : "=r"(r0), "=r"(r1), "=r"(r2), "=r"(r3) : "r"(addr));
}
__device__ __forceinline__ void mma16816(float* c, const uint32_t* a, const uint32_t* b) {
    asm volatile("mma.sync.aligned.m16n8k16.row.col.f32.f16.f16.f32 "
                 "{%0,%1,%2,%3}, {%4,%5,%6,%7}, {%8,%9}, {%0,%1,%2,%3};"
                 : "+f"(c[0]), "+f"(c[1]), "+f"(c[2]), "+f"(c[3])
                 : "r"(a[0]), "r"(a[1]), "r"(a[2]), "r"(a[3]), "r"(b[0]), "r"(b[1]));
}

__device__ __forceinline__ void load_a4(uint32_t f[4][4], uint32_t base, uint32_t offb) {
    #pragma unroll
    for (int mt = 0; mt < 4; mt++)
        ldsm4(f[mt][0], f[mt][1], f[mt][2], f[mt][3], base + offb + (uint32_t)(mt * 2048));
}
__device__ __forceinline__ void load_b2(uint32_t f[4][2], uint32_t base, uint32_t offb) {
    uint32_t r0, r1, r2, r3;
    ldsm4(r0, r1, r2, r3, base + offb);
    f[0][0] = r0; f[0][1] = r1; f[1][0] = r2; f[1][1] = r3;
    ldsm4(r0, r1, r2, r3, base + offb + 2048);          // +16 rows
    f[2][0] = r0; f[2][1] = r1; f[3][0] = r2; f[3][1] = r3;
}
__device__ __forceinline__ void mma_tile(float acc[4][4][4], uint32_t A[4][4], uint32_t B[4][2]) {
    #pragma unroll
    for (int mt = 0; mt < 4; mt++)
        #pragma unroll
        for (int nt = 0; nt < 4; nt++)
            mma16816(acc[mt][nt], A[mt], B[nt]);
}

__device__ __forceinline__ void issue_stage(uint32_t sbase,
    const __half* gA, const __half* gB, int K32, uint32_t so0)
{
    #pragma unroll
    for (int i = 0; i < 4; i++) {
        cp16(sbase + so0 + (uint32_t)(i * 4096),          gA + i * K32);
        cp16(sbase + TILE_B + so0 + (uint32_t)(i * 4096), gB + i * K32);
    }
}

// Epilogue MODE:
//  0: u = acc+bias0 -> oh (fp16, width HH) ; gate = sigmoid(acc+bias1) -> oh2 (fp16, width HH)
//  1/3: out0 = res + acc + bias0 (fp32)
//  2: silu(acc+bias0) -> oh (fp16, width H2)
template <int MODE>
__device__ __forceinline__ void epi_pair(int r, int c, float v0, float v1,
    const float* __restrict__ bias0, const float* __restrict__ bias1,
    const float* __restrict__ res, float* __restrict__ out0,
    __half* __restrict__ oh, __half* __restrict__ oh2)
{
    size_t mg = (size_t)r;
    if (MODE == 0) {
        if (c < HH) {
            __half2 p;
            p.x = __float2half(v0 + bias0[c]);
            p.y = __float2half(v1 + bias0[c+1]);
            *reinterpret_cast<__half2*>(oh + mg*HH + c) = p;
        } else {
            int cc = c - HH;
            __half2 p;
            p.x = __float2half(sigm(v0 + bias1[cc]));
            p.y = __float2half(sigm(v1 + bias1[cc+1]));
            *reinterpret_cast<__half2*>(oh2 + mg*HH + cc) = p;
        }
    } else if (MODE == 1 || MODE == 3) {
        float2 rr = *reinterpret_cast<const float2*>(res + mg*HH + c);
        float2 o = make_float2(rr.x + v0 + bias0[c], rr.y + v1 + bias0[c+1]);
        *reinterpret_cast<float2*>(out0 + mg*HH + c) = o;
    } else { // MODE 2
        float t0 = v0 + bias0[c], t1 = v1 + bias0[c+1];
        __half2 p;
        p.x = __float2half(t0 * sigm(t0));
        p.y = __float2half(t1 * sigm(t1));
        *reinterpret_cast<__half2*>(oh + mg*H2 + c) = p;
    }
}

template <int MODE>
__global__ void __launch_bounds__(GTHREADS, 2) gemm_fp16_kernel(
    const __half* __restrict__ A, int K,
    const __half* __restrict__ B,
    const float* __restrict__ bias0, const float* __restrict__ bias1,
    const float* __restrict__ res, float* __restrict__ out0,
    __half* __restrict__ oh, __half* __restrict__ oh2)
{
    extern __shared__ char smem[];
    uint32_t sb = smem_u32(smem);
    const int tid = threadIdx.x, wid = tid >> 5, lid = tid & 31;
    const int m0 = blockIdx.y * 128, n0 = blockIdx.x * 128;   // x = n-tile (L2 A-reuse)
    const int wr = wid >> 2, wc = wid & 3;       // warp tile: rows wr*64, cols wc*32
    const int nk = K >> 6;
    const int K32 = K * 32;

    float acc[4][4][4];
    #pragma unroll
    for (int i = 0; i < 4; i++)
        #pragma unroll
        for (int j = 0; j < 4; j++)
            #pragma unroll
            for (int q = 0; q < 4; q++) acc[i][j][q] = 0.f;

    // per-kt fragment read offsets (kt = 0..3, chunk = kt*2 + ch)
    const int rowA = wr*64 + ((lid >> 3) & 1) * 8 + (lid & 7);
    const int chA  = (lid >> 4);
    const int rowB = wc*32 + (lid >> 4) * 8 + (lid & 7);
    const int chB  = ((lid >> 3) & 1);
    uint32_t offA[4], offB[4];
    #pragma unroll
    for (int kt = 0; kt < 4; kt++) {
        offA[kt] = sw_off(rowA, kt*2 + chA);
        offB[kt] = sw_off(rowB, kt*2 + chB);
    }

    // per-thread cp.async pointers (advance 64 elements/chunk)
    const int rowS = tid >> 3, cS = tid & 7;     // 32 rows x 8 chunks per pass
    const uint32_t so0 = sw_off(rowS, cS);
    const __half* gA = A + (size_t)(m0 + rowS) * K + cS * 8;
    const __half* gB = B + (size_t)(n0 + rowS) * K + cS * 8;

    #pragma unroll
    for (int s = 0; s < GSTAGES - 1; s++) {
        issue_stage(sb + s*STAGE_B, gA, gB, K32, so0);
        gA += BKK; gB += BKK;
        CP_COMMIT();
    }

    for (int kc = 0; kc < nk; kc++) {
        CP_WAIT(GSTAGES - 2);
        __syncthreads();
        uint32_t st = sb + (uint32_t)(kc % GSTAGES) * STAGE_B;

        uint32_t A0[4][4], A1[4][4], B0[4][2], B1[4][2];
        // entry fragment loads FIRST (latency partly hidden by cp16 issues below)
        load_a4(A0, st, offA[0]);
        load_b2(B0, st + TILE_B, offB[0]);

        if (kc + GSTAGES - 1 < nk) {
            issue_stage(sb + (uint32_t)((kc + GSTAGES - 1) % GSTAGES) * STAGE_B,
                        gA, gB, K32, so0);
            gA += BKK; gB += BKK;
        }
        CP_COMMIT();

        // 4 kt-halves, double-buffered fragments
        load_a4(A1, st, offA[1]);
        load_b2(B1, st + TILE_B, offB[1]);
        mma_tile(acc, A0, B0);                       // kt0
        load_a4(A0, st, offA[2]);
        load_b2(B0, st + TILE_B, offB[2]);
        mma_tile(acc, A1, B1);                       // kt1
        load_a4(A1, st, offA[3]);
        load_b2(B1, st + TILE_B, offB[3]);
        mma_tile(acc, A0, B0);                       // kt2
        mma_tile(acc, A1, B1);                       // kt3
    }

    #pragma unroll
    for (int mt = 0; mt < 4; mt++)
        #pragma unroll
        for (int nt = 0; nt < 4; nt++) {
            float* a4 = acc[mt][nt];
            int r = m0 + wr*64 + mt*16 + (lid >> 2);
            int c = n0 + wc*32 + nt*8 + ((lid & 3) << 1);
            epi_pair<MODE>(r,     c, a4[0], a4[1], bias0, bias1, res, out0, oh, oh2);
            epi_pair<MODE>(r + 8, c, a4[2], a4[3], bias0, bias1, res, out0, oh, oh2);
        }
}

// ===================== host =====================

extern "C" void kernel_launch(void* const* d_in, const int* in_sizes, int n_in,
                              void* d_out, int out_size) {
    const float* x        = (const float*)d_in[0];
    const float* ln1_w    = (const float*)d_in[1];
    const float* ln1_b    = (const float*)d_in[2];
    const float* W_in     = (const float*)d_in[3];
    const float* b_in     = (const float*)d_in[4];
    const float* W_gate   = (const float*)d_in[5];
    const float* b_gate   = (const float*)d_in[6];
    const float* W_out    = (const float*)d_in[7];
    const float* b_out    = (const float*)d_in[8];
    const float* sdecay   = (const float*)d_in[9];
    const float* ln2_w    = (const float*)d_in[10];
    const float* ln2_b    = (const float*)d_in[11];
    const float* W_ff1    = (const float*)d_in[12];
    const float* b_ff1    = (const float*)d_in[13];
    const float* W_ff2    = (const float*)d_in[14];
    const float* b_ff2    = (const float*)d_in[15];
    float* out = (float*)d_out;

    void *p_hid, *p_u, *p_gate, *p_st, *p_y, *p_h2, *p_ff1;
    void *p_Wug, *p_Wout, *p_Wff1, *p_Wff2;
    void *p_cf, *p_cb, *p_sinf, *p_sinb;
    cudaGetSymbolAddress(&p_hid, g_hid);
    cudaGetSymbolAddress(&p_u, g_u);        cudaGetSymbolAddress(&p_gate, g_gate);
    cudaGetSymbolAddress(&p_st, g_st);      cudaGetSymbolAddress(&p_y, g_y);
    cudaGetSymbolAddress(&p_h2, g_h2);      cudaGetSymbolAddress(&p_ff1, g_ff1);
    cudaGetSymbolAddress(&p_Wug, g_Wug);    cudaGetSymbolAddress(&p_Wout, g_Wout);
    cudaGetSymbolAddress(&p_Wff1, g_Wff1);  cudaGetSymbolAddress(&p_Wff2, g_Wff2);
    cudaGetSymbolAddress(&p_cf, g_cf);      cudaGetSymbolAddress(&p_cb, g_cb);
    cudaGetSymbolAddress(&p_sinf, g_sinf);  cudaGetSymbolAddress(&p_sinb, g_sinb);

    cudaFuncSetAttribute(gemm_fp16_kernel<0>, cudaFuncAttributeMaxDynamicSharedMemorySize, GSMEM_BYTES);
    cudaFuncSetAttribute(gemm_fp16_kernel<1>, cudaFuncAttributeMaxDynamicSharedMemorySize, GSMEM_BYTES);
    cudaFuncSetAttribute(gemm_fp16_kernel<2>, cudaFuncAttributeMaxDynamicSharedMemorySize, GSMEM_BYTES);
    cudaFuncSetAttribute(gemm_fp16_kernel<3>, cudaFuncAttributeMaxDynamicSharedMemorySize, GSMEM_BYTES);

    __half* hid  = (__half*)p_hid;
    __half* u16  = (__half*)p_u;
    __half* gate = (__half*)p_gate;
    __half* st   = (__half*)p_st;
    __half* h2   = (__half*)p_h2;
    __half* ff1  = (__half*)p_ff1;
    __half* Wug  = (__half*)p_Wug;
    __half* Wout = (__half*)p_Wout;
    __half* Wff1 = (__half*)p_Wff1;
    __half* Wff2 = (__half*)p_Wff2;

    // ALL weight transposes in one launch (z selects matrix; oversize blocks exit)
    transpose_all_kernel<<<dim3(H2/32, H2/64, 5), 256>>>(
        W_in, W_gate, W_out, W_ff1, W_ff2, Wug, Wout, Wff1, Wff2);

    // LN1 -> hidden (fp16)
    ln_h_kernel<<<LL, 256>>>(x, ln1_w, ln1_b, hid);

    // G1 fused u/gate (N = 2048), u and gate stored fp16
    gemm_fp16_kernel<0><<<dim3(H2/128, LL/128), GTHREADS, GSMEM_BYTES>>>(
        hid, HH, Wug,
        b_in, b_gate, nullptr, nullptr, u16, gate);

    // scan (half2-vectorized p1/p3)
    scan_p1_kernel<<<dim3(GG, HH2/128), 128>>>(
        (const __half2*)u16, sdecay, (float2*)p_cf, (float2*)p_cb);
    scan_p2_kernel<<<dim3(HH/256, 2), 256>>>(
        (const float*)p_cf, (const float*)p_cb, sdecay, (float*)p_sinf, (float*)p_sinb);
    scan_p3_kernel<<<dim3(GG, HH2/128), 128>>>(
        (const __half2*)u16, (const __half2*)gate, sdecay,
        (const float2*)p_sinf, (const float2*)p_sinb, (__half2*)st);

    // G2: y = x + state@W_out + b_out
    gemm_fp16_kernel<1><<<dim3(HH/128, LL/128), GTHREADS, GSMEM_BYTES>>>(
        st, HH, Wout,
        b_out, nullptr, x, (float*)p_y, nullptr, nullptr);

    // LN2 -> h (fp16)
    ln_h_kernel<<<LL, 256>>>((const float*)p_y, ln2_w, ln2_b, h2);

    // G3: ff1 = silu(h@W_ff1 + b_ff1) -> fp16 (N = 2048)
    gemm_fp16_kernel<2><<<dim3(H2/128, LL/128), GTHREADS, GSMEM_BYTES>>>(
        h2, HH, Wff1,
        b_ff1, nullptr, nullptr, nullptr, ff1, nullptr);

    // G4: out = y + ff1@W_ff2 + b_ff2  (K = 2048)
    gemm_fp16_kernel<3><<<dim3(HH/128, LL/128), GTHREADS, GSMEM_BYTES>>>(
        ff1, H2, Wff2,
        b_ff2, nullptr, (const float*)p_y, out, nullptr, nullptr);
}